// round 1
// baseline (speedup 1.0000x reference)
#include <cuda_runtime.h>
#include <cuda_bf16.h>
#include <math.h>

// Problem constants
#define BATCH 8
#define SEQ   2048
#define CDIM  1024

// GEMM tiling
#define BM 128
#define BN 128
#define BK 16

// Scratch (device globals: allocation inside kernel_launch is forbidden)
__device__ float g_kqv[(size_t)BATCH * SEQ * 3 * CDIM];   // 192 MB  [B*T, 3C]
__device__ float g_S  [(size_t)BATCH * SEQ * SEQ];        // 128 MB  [B, T, T]
__device__ float g_O  [(size_t)BATCH * SEQ * CDIM];       //  64 MB  [B*T, C]

// ---------------------------------------------------------------------------
// Generic 128x128x16 fp32 tiled GEMM, 256 threads, 8x8 per-thread micro-tile.
//   C[bz] = alpha * A[bz] * op(B[bz]) (+ bias)
// TRANS_B:     B accessed as [N][K] row-major (NT gemm, for Q*K^T)
// CAUSAL_SKIP: skip blocks strictly above the diagonal (S = Q K^T)
// CAUSAL_K:    limit k-loop to min(K, (by+1)*BM)   (O = P V)
// All of M, N divisible by 128; K (and causal kEnd) divisible by 16.
// ---------------------------------------------------------------------------
template<bool TRANS_B, bool CAUSAL_SKIP, bool CAUSAL_K, bool HAS_BIAS>
__global__ __launch_bounds__(256)
void gemm_tile(const float* __restrict__ A, const float* __restrict__ B,
               float* __restrict__ C, const float* __restrict__ bias,
               int K, int lda, int ldb, int ldc,
               long sA, long sB, long sC, float alpha)
{
    const int bx = blockIdx.x, by = blockIdx.y, bz = blockIdx.z;
    if (CAUSAL_SKIP && bx > by) return;

    const float* Ab = A + (size_t)bz * sA + (size_t)by * BM * lda;
    const float* Bb = B + (size_t)bz * sB;
    float*       Cb = C + (size_t)bz * sC;
    const int col0 = bx * BN;
    const int row0 = by * BM;
    const int kEnd = CAUSAL_K ? min(K, (by + 1) * BM) : K;

    __shared__ float As[BK][BM];
    __shared__ float Bs[BK][BN];

    const int tid = threadIdx.x;
    // A-tile (and NT B-tile) loader coords: 128 rows x 16 cols, 2 float4/thread
    const int ar = tid >> 2;          // 0..63
    const int ac = (tid & 3) << 2;    // 0,4,8,12
    // NN B-tile loader coords: 16 rows x 128 cols, 2 float4/thread
    const int br = tid >> 5;          // 0..7
    const int bc = (tid & 31) << 2;   // 0..124

    const int tm = (tid >> 4) << 3;   // 0..120
    const int tn = (tid & 15) << 3;   // 0..120

    float acc[8][8];
#pragma unroll
    for (int i = 0; i < 8; i++)
#pragma unroll
        for (int j = 0; j < 8; j++) acc[i][j] = 0.0f;

    for (int k0 = 0; k0 < kEnd; k0 += BK) {
        // Load A tile, store transposed As[k][m]
#pragma unroll
        for (int rr = 0; rr < 2; rr++) {
            const int r = ar + rr * 64;
            float4 v = *(const float4*)(Ab + (size_t)r * lda + (k0 + ac));
            As[ac + 0][r] = v.x; As[ac + 1][r] = v.y;
            As[ac + 2][r] = v.z; As[ac + 3][r] = v.w;
        }
        if (TRANS_B) {
            // B logical [N][K] row-major: load [BN][BK] tile, store transposed
#pragma unroll
            for (int rr = 0; rr < 2; rr++) {
                const int r = ar + rr * 64;
                float4 v = *(const float4*)(Bb + (size_t)(col0 + r) * ldb + (k0 + ac));
                Bs[ac + 0][r] = v.x; Bs[ac + 1][r] = v.y;
                Bs[ac + 2][r] = v.z; Bs[ac + 3][r] = v.w;
            }
        } else {
#pragma unroll
            for (int rr = 0; rr < 2; rr++) {
                const int r = br + rr * 8;
                float4 v = *(const float4*)(Bb + (size_t)(k0 + r) * ldb + (col0 + bc));
                *(float4*)&Bs[r][bc] = v;
            }
        }
        __syncthreads();

#pragma unroll
        for (int kk = 0; kk < BK; kk++) {
            float a[8], b[8];
            *(float4*)&a[0] = *(const float4*)&As[kk][tm];
            *(float4*)&a[4] = *(const float4*)&As[kk][tm + 4];
            *(float4*)&b[0] = *(const float4*)&Bs[kk][tn];
            *(float4*)&b[4] = *(const float4*)&Bs[kk][tn + 4];
#pragma unroll
            for (int i = 0; i < 8; i++)
#pragma unroll
                for (int j = 0; j < 8; j++)
                    acc[i][j] = fmaf(a[i], b[j], acc[i][j]);
        }
        __syncthreads();
    }

    // Epilogue
#pragma unroll
    for (int i = 0; i < 8; i++) {
        const size_t rbase = (size_t)(row0 + tm + i) * ldc;
#pragma unroll
        for (int j4 = 0; j4 < 2; j4++) {
            const int c = col0 + tn + j4 * 4;
            float4 v;
            v.x = acc[i][j4 * 4 + 0] * alpha;
            v.y = acc[i][j4 * 4 + 1] * alpha;
            v.z = acc[i][j4 * 4 + 2] * alpha;
            v.w = acc[i][j4 * 4 + 3] * alpha;
            if (HAS_BIAS) {
                v.x += bias[c + 0]; v.y += bias[c + 1];
                v.z += bias[c + 2]; v.w += bias[c + 3];
            }
            *(float4*)(Cb + rbase + c) = v;
        }
    }
}

// ---------------------------------------------------------------------------
// Causal softmax over row i of S[b] (valid entries j in [0, i]).
// Also zeroes (i, rowblock_end) so GEMM3's block-level causal k-limit is safe.
// One block (256 threads) per (i, b).
// ---------------------------------------------------------------------------
__global__ __launch_bounds__(256)
void softmax_causal(float* __restrict__ S, int T)
{
    const int i = blockIdx.x;
    const int b = blockIdx.y;
    float* row = S + ((size_t)b * T + i) * T;
    const int L = i + 1;
    const int tid = threadIdx.x;

    __shared__ float red[8];
    __shared__ float bval;

    // --- max ---
    float m = -1e30f;
    for (int j = tid; j < L; j += 256) m = fmaxf(m, row[j]);
#pragma unroll
    for (int o = 16; o; o >>= 1) m = fmaxf(m, __shfl_xor_sync(0xffffffffu, m, o));
    if ((tid & 31) == 0) red[tid >> 5] = m;
    __syncthreads();
    if (tid == 0) {
        float mm = red[0];
#pragma unroll
        for (int w = 1; w < 8; w++) mm = fmaxf(mm, red[w]);
        bval = mm;
    }
    __syncthreads();
    m = bval;
    __syncthreads();

    // --- exp & sum ---
    float s = 0.0f;
    for (int j = tid; j < L; j += 256) {
        float e = expf(row[j] - m);
        row[j] = e;
        s += e;
    }
#pragma unroll
    for (int o = 16; o; o >>= 1) s += __shfl_xor_sync(0xffffffffu, s, o);
    if ((tid & 31) == 0) red[tid >> 5] = s;
    __syncthreads();
    if (tid == 0) {
        float ss = 0.0f;
#pragma unroll
        for (int w = 0; w < 8; w++) ss += red[w];
        bval = ss;
    }
    __syncthreads();
    const float inv = 1.0f / bval;

    // --- normalize ---
    for (int j = tid; j < L; j += 256) row[j] *= inv;

    // zero the garbage region (i, end) inside this 128-row block (BM of GEMM3)
    const int end = ((i >> 7) + 1) << 7;
    for (int j = L + tid; j < end; j += 256) row[j] = 0.0f;
}

// ---------------------------------------------------------------------------
extern "C" void kernel_launch(void* const* d_in, const int* in_sizes, int n_in,
                              void* d_out, int out_size)
{
    (void)in_sizes; (void)n_in; (void)out_size;
    const float* x      = (const float*)d_in[0];  // [B,T,C]
    const float* W_kqv  = (const float*)d_in[1];  // [C,3C]
    const float* b_kqv  = (const float*)d_in[2];  // [3C]
    const float* W_proj = (const float*)d_in[3];  // [C,C]
    const float* b_proj = (const float*)d_in[4];  // [C]
    float* out = (float*)d_out;                   // [1,B,T,C] contiguous

    float *kqv, *S, *O;
    cudaGetSymbolAddress((void**)&kqv, g_kqv);
    cudaGetSymbolAddress((void**)&S,   g_S);
    cudaGetSymbolAddress((void**)&O,   g_O);

    const int B = BATCH, T = SEQ, C = CDIM;
    const float scale = 1.0f / sqrtf((float)T);   // reference scales by 1/sqrt(T)
    const long sBT3C = (long)T * 3 * C;

    // 1) kqv = x @ W_kqv + b_kqv     [16384, 3072]
    gemm_tile<false, false, false, true><<<dim3(3 * C / BN, B * T / BM, 1), 256>>>(
        x, W_kqv, kqv, b_kqv, C, C, 3 * C, 3 * C, 0, 0, 0, 1.0f);

    // 2) S = Q @ K^T * scale (per batch, skip blocks above diagonal)
    //    columns of kqv: [0,C)=K, [C,2C)=Q, [2C,3C)=V
    gemm_tile<true, true, false, false><<<dim3(T / BN, T / BM, B), 256>>>(
        kqv + C /*Q*/, kqv /*K*/, S, nullptr,
        C, 3 * C, 3 * C, T, sBT3C, sBT3C, (long)T * T, scale);

    // 3) causal softmax rows
    softmax_causal<<<dim3(T, B, 1), 256>>>(S, T);

    // 4) O = P @ V (per batch, causal k-limit)
    gemm_tile<false, false, true, false><<<dim3(C / BN, T / BM, B), 256>>>(
        S, kqv + 2 * C /*V*/, O, nullptr,
        T, T, 3 * C, C, (long)T * T, sBT3C, (long)T * C, 1.0f);

    // 5) out = O @ W_proj + b_proj   [16384, 1024]
    gemm_tile<false, false, false, true><<<dim3(C / BN, B * T / BM, 1), 256>>>(
        O, W_proj, out, b_proj, C, C, C, C, 0, 0, 0, 1.0f);
}

// round 3
// speedup vs baseline: 3.4886x; 3.4886x over previous
#include <cuda_runtime.h>
#include <cstdint>
#include <math.h>

// ---------------------------------------------------------------- constants
#define BATCH 8
#define SEQ   2048
#define CDIM  1024

#define BM 128
#define BN 128
#define BKK 32                      // tf32 per stage row = 128 bytes
#define NSTAGES 3
#define STAGE_BYTES (2*BM*128)      // A tile 16KB + B tile 16KB
#define SMEM_DYN (NSTAGES*STAGE_BYTES + 1024)

#define SWZ(x) ((x) ^ (((x)>>3)&0x70))

// ---------------------------------------------------------------- scratch
__device__ float g_kqv[(size_t)BATCH*SEQ*3*CDIM];  // [B*T, 3C]
__device__ float g_S  [(size_t)BATCH*SEQ*SEQ];     // [B, T, T]
__device__ float g_O  [(size_t)BATCH*SEQ*CDIM];    // [B*T, C]
__device__ float g_Wt [(size_t)3*CDIM*CDIM];       // W_kqv^T  [3C, C]
__device__ float g_WtP[(size_t)CDIM*CDIM];         // W_proj^T [C, C]
__device__ float g_Vt [(size_t)BATCH*CDIM*SEQ];    // V^T per batch [C, T]

// ---------------------------------------------------------------- ptx utils
__device__ __forceinline__ uint32_t smem_u32(const void* p){
    uint32_t a;
    asm("{ .reg .u64 t; cvta.to.shared.u64 t, %1; cvt.u32.u64 %0, t; }"
        : "=r"(a) : "l"(p));
    return a;
}
__device__ __forceinline__ void cp16(uint32_t dst, const void* src){
    asm volatile("cp.async.ca.shared.global [%0], [%1], 16;" :: "r"(dst), "l"(src));
}
#define CP_COMMIT() asm volatile("cp.async.commit_group;" ::: "memory")
#define CP_WAIT2()  asm volatile("cp.async.wait_group 2;" ::: "memory")

__device__ __forceinline__ void ldm_x4(uint32_t& r0, uint32_t& r1,
                                       uint32_t& r2, uint32_t& r3, uint32_t a){
    asm volatile("ldmatrix.sync.aligned.m8n8.x4.shared.b16 {%0,%1,%2,%3}, [%4];"
        : "=r"(r0), "=r"(r1), "=r"(r2), "=r"(r3) : "r"(a));
}
#define CVT_TF32(x) asm volatile("cvt.rna.tf32.f32 %0, %0;" : "+r"(x))

__device__ __forceinline__ void mma_m16n8k8(float* c, const uint32_t* a,
                                            uint32_t b0, uint32_t b1){
    asm volatile(
        "mma.sync.aligned.m16n8k8.row.col.f32.tf32.tf32.f32 "
        "{%0,%1,%2,%3}, {%4,%5,%6,%7}, {%8,%9}, {%0,%1,%2,%3};"
        : "+f"(c[0]), "+f"(c[1]), "+f"(c[2]), "+f"(c[3])
        : "r"(a[0]), "r"(a[1]), "r"(a[2]), "r"(a[3]), "r"(b0), "r"(b1));
}

// ---------------------------------------------------------------- tile loader
// A-tile: 128 rows x 32 fp32 (128B rows, SW128-swizzled), B-tile same.
// 256 threads, 4 x cp.async(16B) each per tile.
__device__ __forceinline__ void load_tile(uint32_t sA, uint32_t sB,
    const float* __restrict__ Ab, const float* __restrict__ Bb,
    int lda, int ldb, int k0, int tid)
{
#pragma unroll
    for (int i = 0; i < 4; i++) {
        int idx = tid + i*256;
        int row = idx >> 3;
        int ck  = (idx & 7) << 2;
        uint32_t so = SWZ((uint32_t)(row*128 + ck*4));
        cp16(sA + so, Ab + (size_t)row*lda + k0 + ck);
        cp16(sB + so, Bb + (size_t)row*ldb + k0 + ck);
    }
}

// ---------------------------------------------------------------- mma GEMM
// C[bz][m][n] = alpha * sum_k A[bz][m][k] * B[bz][n][k]  (+ bias[n])
// A: [M,K] row-major (lda), B: [N,K] row-major (ldb) — NT gemm, tf32 tensor.
template<bool CSKIP, bool CK, bool HB>
__global__ void __launch_bounds__(256) gemm_tc(
    const float* __restrict__ A, const float* __restrict__ B,
    float* __restrict__ C, const float* __restrict__ bias,
    int K, int lda, int ldb, int ldc, long sA, long sB, long sC, float alpha)
{
    const int bx = blockIdx.x, by = blockIdx.y, bz = blockIdx.z;
    if (CSKIP && bx > by) return;

    extern __shared__ char smem[];
    const uint32_t tb = (smem_u32(smem) + 1023) & ~1023u;
    const int tid = threadIdx.x, wid = tid >> 5, lid = tid & 31;
    const int wm = wid & 1;        // 2 m-blocks of 64
    const int wn = wid >> 1;       // 4 n-blocks of 32

    const float* Ab = A + (size_t)bz*sA + (size_t)by*BM*lda;
    const float* Bb = B + (size_t)bz*sB + (size_t)bx*BN*ldb;
    float* Cb = C + (size_t)bz*sC;
    const int kEnd = CK ? min(K, (by+1)*BM) : K;
    const int iters = kEnd >> 5;                 // multiple of 4, >= NSTAGES

    float acc[4][4][4];
#pragma unroll
    for (int i = 0; i < 4; i++)
#pragma unroll
        for (int j = 0; j < 4; j++)
#pragma unroll
            for (int r = 0; r < 4; r++) acc[i][j][r] = 0.0f;

    // precomputed ldmatrix lane row bases (bytes within tile)
    // A tile i: rows wm*64 + i*16 + (lid&15); col byte = kchunk*32 + (lid>>4)*16
    const uint32_t aRow  = (uint32_t)((wm*64 + (lid & 15)) * 128);
    const uint32_t aKoff = (uint32_t)((lid >> 4) * 16);
    // B pair p: rows wn*32 + p*16 + (lid&7) + (lid>>4)*8 ; col byte = kchunk*32 + ((lid>>3)&1)*16
    const uint32_t bRow  = (uint32_t)((wn*32 + (lid & 7) + ((lid >> 4) * 8)) * 128);
    const uint32_t bKoff = (uint32_t)(((lid >> 3) & 1) * 16);

    // prologue
#pragma unroll
    for (int s = 0; s < NSTAGES; s++) {
        load_tile(tb + s*STAGE_BYTES, tb + s*STAGE_BYTES + 16384,
                  Ab, Bb, lda, ldb, s*BKK, tid);
        CP_COMMIT();
    }

    for (int it = 0; it < iters; ++it) {
        const int s = it % NSTAGES;
        const uint32_t sAb = tb + s*STAGE_BYTES;
        const uint32_t sBb = sAb + 16384;
        CP_WAIT2();
        __syncthreads();

#pragma unroll
        for (int kc = 0; kc < 4; kc++) {
            const uint32_t kb = (uint32_t)(kc * 32);
            uint32_t a[4][4];
#pragma unroll
            for (int i = 0; i < 4; i++) {
                uint32_t off = aRow + (uint32_t)(i*16*128) + kb + aKoff;
                ldm_x4(a[i][0], a[i][1], a[i][2], a[i][3], sAb + SWZ(off));
            }
            uint32_t b[2][4];
#pragma unroll
            for (int p = 0; p < 2; p++) {
                uint32_t off = bRow + (uint32_t)(p*16*128) + kb + bKoff;
                ldm_x4(b[p][0], b[p][1], b[p][2], b[p][3], sBb + SWZ(off));
            }
#pragma unroll
            for (int i = 0; i < 4; i++) {
                CVT_TF32(a[i][0]); CVT_TF32(a[i][1]);
                CVT_TF32(a[i][2]); CVT_TF32(a[i][3]);
            }
#pragma unroll
            for (int p = 0; p < 2; p++) {
                CVT_TF32(b[p][0]); CVT_TF32(b[p][1]);
                CVT_TF32(b[p][2]); CVT_TF32(b[p][3]);
            }
#pragma unroll
            for (int i = 0; i < 4; i++)
#pragma unroll
                for (int j = 0; j < 4; j++)
                    mma_m16n8k8(acc[i][j], a[i],
                                b[j >> 1][(j & 1)*2], b[j >> 1][(j & 1)*2 + 1]);
        }

        __syncthreads();
        const int nit = it + NSTAGES;
        if (nit < iters)
            load_tile(tb + s*STAGE_BYTES, tb + s*STAGE_BYTES + 16384,
                      Ab, Bb, lda, ldb, nit*BKK, tid);
        CP_COMMIT();
    }

    // epilogue: c0/c1 at (row, col..col+1), c2/c3 at (row+8, ...)
    const int rowg = by*BM + wm*64 + (lid >> 2);
    const int colg = bx*BN + wn*32 + (lid & 3)*2;
#pragma unroll
    for (int j = 0; j < 4; j++) {
        const int c = colg + j*8;
        float2 bv = make_float2(0.f, 0.f);
        if (HB) bv = *(const float2*)(bias + c);
#pragma unroll
        for (int i = 0; i < 4; i++) {
            const int r = rowg + i*16;
            float2 v0, v1;
            v0.x = acc[i][j][0]*alpha + bv.x;
            v0.y = acc[i][j][1]*alpha + bv.y;
            v1.x = acc[i][j][2]*alpha + bv.x;
            v1.y = acc[i][j][3]*alpha + bv.y;
            *(float2*)(Cb + (size_t)r*ldc + c)       = v0;
            *(float2*)(Cb + (size_t)(r+8)*ldc + c)   = v1;
        }
    }
}

// ---------------------------------------------------------------- transpose
__global__ void __launch_bounds__(256) transpose_g(
    const float* __restrict__ in, float* __restrict__ out,
    int ldin, int ldout, long sIn, long sOut)
{
    __shared__ float t[32][33];
    const int b = blockIdx.z;
    in  += (size_t)b * sIn;
    out += (size_t)b * sOut;
    const int x = blockIdx.x * 32;
    const int y = blockIdx.y * 32;
#pragma unroll
    for (int j = threadIdx.y; j < 32; j += 8)
        t[j][threadIdx.x] = in[(size_t)(y + j)*ldin + x + threadIdx.x];
    __syncthreads();
#pragma unroll
    for (int j = threadIdx.y; j < 32; j += 8)
        out[(size_t)(x + j)*ldout + y + threadIdx.x] = t[threadIdx.x][j];
}

// ---------------------------------------------------------------- softmax
__global__ __launch_bounds__(256)
void softmax_causal(float* __restrict__ S, int T)
{
    const int i = blockIdx.x;
    const int b = blockIdx.y;
    float* row = S + ((size_t)b*T + i)*T;
    const int L = i + 1;
    const int tid = threadIdx.x;

    __shared__ float red[8];
    __shared__ float bval;

    float m = -1e30f;
    for (int j = tid; j < L; j += 256) m = fmaxf(m, row[j]);
#pragma unroll
    for (int o = 16; o; o >>= 1) m = fmaxf(m, __shfl_xor_sync(0xffffffffu, m, o));
    if ((tid & 31) == 0) red[tid >> 5] = m;
    __syncthreads();
    if (tid == 0) {
        float mm = red[0];
#pragma unroll
        for (int w = 1; w < 8; w++) mm = fmaxf(mm, red[w]);
        bval = mm;
    }
    __syncthreads();
    m = bval;
    __syncthreads();

    float s = 0.0f;
    for (int j = tid; j < L; j += 256) {
        float e = expf(row[j] - m);
        row[j] = e;
        s += e;
    }
#pragma unroll
    for (int o = 16; o; o >>= 1) s += __shfl_xor_sync(0xffffffffu, s, o);
    if ((tid & 31) == 0) red[tid >> 5] = s;
    __syncthreads();
    if (tid == 0) {
        float ss = 0.0f;
#pragma unroll
        for (int w = 0; w < 8; w++) ss += red[w];
        bval = ss;
    }
    __syncthreads();
    const float inv = 1.0f / bval;

    for (int j = tid; j < L; j += 256) row[j] *= inv;
    const int end = ((i >> 7) + 1) << 7;   // zero to 128-block end for PV gemm
    for (int j = L + tid; j < end; j += 256) row[j] = 0.0f;
}

// ---------------------------------------------------------------- launch
extern "C" void kernel_launch(void* const* d_in, const int* in_sizes, int n_in,
                              void* d_out, int out_size)
{
    (void)in_sizes; (void)n_in; (void)out_size;
    const float* x      = (const float*)d_in[0];
    const float* W_kqv  = (const float*)d_in[1];
    const float* b_kqv  = (const float*)d_in[2];
    const float* W_proj = (const float*)d_in[3];
    const float* b_proj = (const float*)d_in[4];
    float* out = (float*)d_out;

    float *kqv, *S, *O, *Wt, *WtP, *Vt;
    cudaGetSymbolAddress((void**)&kqv, g_kqv);
    cudaGetSymbolAddress((void**)&S,   g_S);
    cudaGetSymbolAddress((void**)&O,   g_O);
    cudaGetSymbolAddress((void**)&Wt,  g_Wt);
    cudaGetSymbolAddress((void**)&WtP, g_WtP);
    cudaGetSymbolAddress((void**)&Vt,  g_Vt);

    const int B = BATCH, T = SEQ, C = CDIM;
    const float scale = 1.0f / sqrtf((float)T);
    const long sBT3C = (long)T*3*C;

    cudaFuncSetAttribute(gemm_tc<false,false,true>,
        cudaFuncAttributeMaxDynamicSharedMemorySize, SMEM_DYN);
    cudaFuncSetAttribute(gemm_tc<true,false,false>,
        cudaFuncAttributeMaxDynamicSharedMemorySize, SMEM_DYN);
    cudaFuncSetAttribute(gemm_tc<false,true,false>,
        cudaFuncAttributeMaxDynamicSharedMemorySize, SMEM_DYN);

    // weight transposes
    transpose_g<<<dim3(3*C/32, C/32, 1), dim3(32,8)>>>(W_kqv, Wt, 3*C, C, 0, 0);
    transpose_g<<<dim3(C/32,   C/32, 1), dim3(32,8)>>>(W_proj, WtP, C, C, 0, 0);

    // 1) kqv = x @ W_kqv + b_kqv
    gemm_tc<false,false,true><<<dim3(3*C/BN, (B*T)/BM, 1), 256, SMEM_DYN>>>(
        x, Wt, kqv, b_kqv, C, C, C, 3*C, 0, 0, 0, 1.0f);

    // transpose V per batch: Vt[b][c][t] = kqv[b*T+t][2C+c]
    transpose_g<<<dim3(C/32, T/32, B), dim3(32,8)>>>(
        kqv + 2*C, Vt, 3*C, T, sBT3C, (long)C*T);

    // 2) S = Q @ K^T * scale (causal block-skip)
    gemm_tc<true,false,false><<<dim3(T/BN, T/BM, B), 256, SMEM_DYN>>>(
        kqv + C, kqv, S, nullptr, C, 3*C, 3*C, T,
        sBT3C, sBT3C, (long)T*T, scale);

    // 3) causal softmax
    softmax_causal<<<dim3(T, B, 1), 256>>>(S, T);

    // 4) O = P @ V (causal k-limit; B = Vt [C,T])
    gemm_tc<false,true,false><<<dim3(C/BN, T/BM, B), 256, SMEM_DYN>>>(
        S, Vt, O, nullptr, T, T, T, C,
        (long)T*T, (long)C*T, (long)T*C, 1.0f);

    // 5) out = O @ W_proj + b_proj
    gemm_tc<false,false,true><<<dim3(C/BN, (B*T)/BM, 1), 256, SMEM_DYN>>>(
        O, WtP, out, b_proj, C, C, C, C, 0, 0, 0, 1.0f);
}